// round 4
// baseline (speedup 1.0000x reference)
#include <cuda_runtime.h>

#define BB 4
#define LQ 256
#define LK 256
#define DD 768

// Scratch (no cudaMalloc allowed)
__device__ float g_q[BB*LQ*DD];
__device__ float g_k[BB*LK*DD];
__device__ float g_v[BB*LK*DD];
__device__ float g_scores[BB*LQ*LK];

__device__ __forceinline__ float tanh_fast(float x) {
    float y;
    asm("tanh.approx.f32 %0, %1;" : "=f"(y) : "f"(x));
    return y;
}

// ---- packed fp32x2 helpers (Blackwell FFMA2 path) ----
__device__ __forceinline__ unsigned long long pack2(float lo, float hi) {
    unsigned long long r;
    asm("mov.b64 %0, {%1, %2};" : "=l"(r) : "f"(lo), "f"(hi));
    return r;
}
__device__ __forceinline__ void ffma2(unsigned long long& acc,
                                      unsigned long long a,
                                      unsigned long long b) {
    asm("fma.rn.f32x2 %0, %1, %2, %0;" : "+l"(acc) : "l"(a), "l"(b));
}
__device__ __forceinline__ float2 unpack2(unsigned long long v) {
    float lo, hi;
    asm("mov.b64 {%0, %1}, %2;" : "=f"(lo), "=f"(hi) : "l"(v));
    return make_float2(lo, hi);
}

// ---------------------------------------------------------------------------
// Projection GEMM: Out[M,N] = X[M,K] @ W[K,N] + b[N].  M=1024, N=K=768.
// 128x128 tile, 512 threads (16 warps/SM), BK=16 double-buffered, single sync.
// Micro: 4m x 8n per thread, FFMA2 pairs along n.
// ---------------------------------------------------------------------------
__global__ __launch_bounds__(512) void proj_kernel(
    const float* __restrict__ xq, const float* __restrict__ xk, const float* __restrict__ xv,
    const float* __restrict__ Wq, const float* __restrict__ bq,
    const float* __restrict__ Wk, const float* __restrict__ bk,
    const float* __restrict__ Wv, const float* __restrict__ bv)
{
    const int N = DD, K = DD;
    const float *X, *W, *bias;
    float* Out;
    if (blockIdx.z == 0)      { X = xq; W = Wq; bias = bq; Out = g_q; }
    else if (blockIdx.z == 1) { X = xk; W = Wk; bias = bk; Out = g_k; }
    else                      { X = xv; W = Wv; bias = bv; Out = g_v; }

    __shared__ float As[2][16][128];   // A transposed: As[k][m]
    __shared__ float Bs[2][16][128];   // Bs[k][n]

    const int t  = threadIdx.x;        // 0..511
    const int tx = t & 15;             // n: tx*8 (8 cols)
    const int ty = t >> 4;             // 0..31, m: ty*4 (4 rows)
    const int m0 = blockIdx.y * 128;
    const int n0 = blockIdx.x * 128;

    unsigned long long acc[4][4];      // 4 m x 4 n-pairs
    #pragma unroll
    for (int i = 0; i < 4; i++)
        #pragma unroll
        for (int p = 0; p < 4; p++) acc[i][p] = 0ull;

    // A load: 128 rows x 16 cols, 1 float4 per thread
    const int lr = t >> 2, lc = (t & 3) * 4;
    // B load: 16 rows x 128 cols, 1 float4 per thread
    const int wr = t >> 5, wc = (t & 31) * 4;

    const float* Xp = X + (size_t)(m0 + lr) * K + lc;
    const float* Wp = W + (size_t)wr * N + n0 + wc;

    float4 pa = *(const float4*)(Xp);
    float4 pb = *(const float4*)(Wp);

    int buf = 0;
    for (int k0 = 0; k0 < K; k0 += 16) {
        As[buf][lc+0][lr] = pa.x; As[buf][lc+1][lr] = pa.y;
        As[buf][lc+2][lr] = pa.z; As[buf][lc+3][lr] = pa.w;
        *(float4*)&Bs[buf][wr][wc] = pb;
        __syncthreads();

        if (k0 + 16 < K) {
            pa = *(const float4*)(Xp + k0 + 16);
            pb = *(const float4*)(Wp + (size_t)(k0 + 16) * N);
        }

        #pragma unroll
        for (int kk = 0; kk < 16; kk++) {
            float a[4];
            *(float4*)&a[0] = *(const float4*)&As[buf][kk][ty*4];   // broadcast (2 addrs/warp)
            ulonglong2 b01 = *(const ulonglong2*)&Bs[buf][kk][tx*8];
            ulonglong2 b23 = *(const ulonglong2*)&Bs[buf][kk][tx*8 + 4];
            unsigned long long bb[4] = { b01.x, b01.y, b23.x, b23.y };
            #pragma unroll
            for (int i = 0; i < 4; i++) {
                unsigned long long aa = pack2(a[i], a[i]);
                #pragma unroll
                for (int p = 0; p < 4; p++) ffma2(acc[i][p], aa, bb[p]);
            }
        }
        buf ^= 1;
    }

    #pragma unroll
    for (int i = 0; i < 4; i++) {
        const int m = m0 + ty*4 + i;
        const int n = n0 + tx*8;
        float2 p0 = unpack2(acc[i][0]);
        float2 p1 = unpack2(acc[i][1]);
        float2 p2 = unpack2(acc[i][2]);
        float2 p3 = unpack2(acc[i][3]);
        float4 r0, r1;
        r0.x = p0.x + bias[n+0]; r0.y = p0.y + bias[n+1];
        r0.z = p1.x + bias[n+2]; r0.w = p1.y + bias[n+3];
        r1.x = p2.x + bias[n+4]; r1.y = p2.y + bias[n+5];
        r1.z = p3.x + bias[n+6]; r1.w = p3.y + bias[n+7];
        *(float4*)&Out[(size_t)m * N + n]     = r0;
        *(float4*)&Out[(size_t)m * N + n + 4] = r1;
    }
}

// ---------------------------------------------------------------------------
// Scores: s[b,i,j] = sum_d Ws[d]*tanh(q[b,i,d]+k[b,j,d]) + bs  (MUFU-bound)
// ---------------------------------------------------------------------------
__global__ __launch_bounds__(256) void score_kernel(const float* __restrict__ Ws,
                                                    const float* __restrict__ bsp)
{
    const int bz = blockIdx.z;
    const int q0 = blockIdx.y * 32;
    const int k0 = blockIdx.x * 32;

    __shared__ float Qs[32][65];
    __shared__ float Ks[32][65];
    __shared__ float Wss[64];

    const int t  = threadIdx.x;
    const int tx = t & 15, ty = t >> 4;

    float acc00 = 0.f, acc01 = 0.f, acc10 = 0.f, acc11 = 0.f;

    const float* qb = g_q + ((size_t)bz*LQ + q0) * DD;
    const float* kb = g_k + ((size_t)bz*LK + k0) * DD;

    const int lrow = t >> 3;
    const int lcol = (t & 7) * 8;

    for (int d0 = 0; d0 < DD; d0 += 64) {
        float4 x0 = *(const float4*)&qb[(size_t)lrow*DD + d0 + lcol];
        float4 x1 = *(const float4*)&qb[(size_t)lrow*DD + d0 + lcol + 4];
        Qs[lrow][lcol+0] = x0.x; Qs[lrow][lcol+1] = x0.y;
        Qs[lrow][lcol+2] = x0.z; Qs[lrow][lcol+3] = x0.w;
        Qs[lrow][lcol+4] = x1.x; Qs[lrow][lcol+5] = x1.y;
        Qs[lrow][lcol+6] = x1.z; Qs[lrow][lcol+7] = x1.w;
        float4 y0 = *(const float4*)&kb[(size_t)lrow*DD + d0 + lcol];
        float4 y1 = *(const float4*)&kb[(size_t)lrow*DD + d0 + lcol + 4];
        Ks[lrow][lcol+0] = y0.x; Ks[lrow][lcol+1] = y0.y;
        Ks[lrow][lcol+2] = y0.z; Ks[lrow][lcol+3] = y0.w;
        Ks[lrow][lcol+4] = y1.x; Ks[lrow][lcol+5] = y1.y;
        Ks[lrow][lcol+6] = y1.z; Ks[lrow][lcol+7] = y1.w;
        if (t < 16) *(float4*)&Wss[t*4] = *(const float4*)&Ws[d0 + t*4];
        __syncthreads();

        #pragma unroll 16
        for (int d = 0; d < 64; d++) {
            const float w  = Wss[d];
            const float qa = Qs[ty*2+0][d];
            const float qc = Qs[ty*2+1][d];
            const float ka = Ks[tx*2+0][d];
            const float kc = Ks[tx*2+1][d];
            acc00 = fmaf(w, tanh_fast(qa + ka), acc00);
            acc01 = fmaf(w, tanh_fast(qa + kc), acc01);
            acc10 = fmaf(w, tanh_fast(qc + ka), acc10);
            acc11 = fmaf(w, tanh_fast(qc + kc), acc11);
        }
        __syncthreads();
    }

    const float bsv = *bsp;
    float* sp = g_scores + ((size_t)bz*LQ + q0) * LK + k0;
    sp[(ty*2+0)*LK + tx*2+0] = acc00 + bsv;
    sp[(ty*2+0)*LK + tx*2+1] = acc01 + bsv;
    sp[(ty*2+1)*LK + tx*2+0] = acc10 + bsv;
    sp[(ty*2+1)*LK + tx*2+1] = acc11 + bsv;
}

// ---------------------------------------------------------------------------
// Row softmax over LK=256. One block (256 threads) per (b,q) row.
// ---------------------------------------------------------------------------
__global__ __launch_bounds__(256) void softmax_kernel(float* __restrict__ wout)
{
    const int row = blockIdx.x;
    const int t   = threadIdx.x;
    __shared__ float red[8];

    const float v = g_scores[(size_t)row*LK + t];

    float m = v;
    #pragma unroll
    for (int o = 16; o > 0; o >>= 1) m = fmaxf(m, __shfl_xor_sync(0xffffffffu, m, o));
    if ((t & 31) == 0) red[t >> 5] = m;
    __syncthreads();
    float mx = red[0];
    #pragma unroll
    for (int i = 1; i < 8; i++) mx = fmaxf(mx, red[i]);
    __syncthreads();

    const float e = __expf(v - mx);
    float s = e;
    #pragma unroll
    for (int o = 16; o > 0; o >>= 1) s += __shfl_xor_sync(0xffffffffu, s, o);
    if ((t & 31) == 0) red[t >> 5] = s;
    __syncthreads();
    float sum = 0.f;
    #pragma unroll
    for (int i = 0; i < 8; i++) sum += red[i];

    wout[(size_t)row*LK + t] = e * (1.0f / sum);
}

// ---------------------------------------------------------------------------
// attended[b,i,:] = sum_j w[b,i,j] * v[b,j,:]
// Block = (batch b, 8 q-rows). 384 threads = 12 warps; warp w owns d-slice
// [w*64, w*64+64), each lane a d-pair. Weights staged DUPLICATED in smem
// ({w,w} pairs -> LDS.128 gives 2 FFMA2 a-operands, all-broadcast).
// j-loop is barrier-free; V streamed from L2 via LDG.64.
// grid (32, 4) = 128 blocks.
// ---------------------------------------------------------------------------
__global__ __launch_bounds__(384) void av_kernel(const float* __restrict__ wts,
                                                 float* __restrict__ out)
{
    const int b  = blockIdx.y;
    const int q0 = blockIdx.x * 8;

    __shared__ float Wd[256][16];   // Wd[j][2*qi] = Wd[j][2*qi+1] = w[b][q0+qi][j]

    const int t = threadIdx.x;      // 0..383

    // stage duplicated weights (one pass, one barrier)
    for (int idx = t; idx < 8 * 256; idx += 384) {
        const int qi = idx >> 8, j = idx & 255;
        const float w = wts[((size_t)b*LQ + q0 + qi) * LK + j];
        Wd[j][2*qi+0] = w;
        Wd[j][2*qi+1] = w;
    }
    __syncthreads();

    const int lane = t & 31;
    const int wrp  = t >> 5;               // 0..11
    const int d    = wrp * 64 + lane * 2;  // even -> 8B aligned

    const float* vp = g_v + (size_t)b * LK * DD + d;

    unsigned long long acc[8];
    #pragma unroll
    for (int i = 0; i < 8; i++) acc[i] = 0ull;

    #pragma unroll 4
    for (int j = 0; j < LK; j++) {
        const unsigned long long vv = *(const unsigned long long*)(vp + (size_t)j * DD);
        ulonglong2 w01 = *(const ulonglong2*)&Wd[j][0];   // {w0,w0},{w1,w1}
        ulonglong2 w23 = *(const ulonglong2*)&Wd[j][4];
        ulonglong2 w45 = *(const ulonglong2*)&Wd[j][8];
        ulonglong2 w67 = *(const ulonglong2*)&Wd[j][12];
        ffma2(acc[0], w01.x, vv);
        ffma2(acc[1], w01.y, vv);
        ffma2(acc[2], w23.x, vv);
        ffma2(acc[3], w23.y, vv);
        ffma2(acc[4], w45.x, vv);
        ffma2(acc[5], w45.y, vv);
        ffma2(acc[6], w67.x, vv);
        ffma2(acc[7], w67.y, vv);
    }

    #pragma unroll
    for (int qi = 0; qi < 8; qi++) {
        float2 p = unpack2(acc[qi]);
        float* op = out + ((size_t)b*LQ + q0 + qi) * DD + d;
        *(float2*)op = p;
    }
}

// ---------------------------------------------------------------------------
extern "C" void kernel_launch(void* const* d_in, const int* in_sizes, int n_in,
                              void* d_out, int out_size)
{
    const float* query = (const float*)d_in[0];
    const float* key   = (const float*)d_in[1];
    const float* value = (const float*)d_in[2];
    const float* Wq    = (const float*)d_in[3];
    const float* bq    = (const float*)d_in[4];
    const float* Wk    = (const float*)d_in[5];
    const float* bk    = (const float*)d_in[6];
    const float* Wv    = (const float*)d_in[7];
    const float* bv    = (const float*)d_in[8];
    const float* Ws    = (const float*)d_in[9];
    const float* bs    = (const float*)d_in[10];

    float* att = (float*)d_out;                  // [B,LQ,D]
    float* wts = att + (size_t)BB * LQ * DD;     // [B,LQ,LK]

    proj_kernel<<<dim3(DD/128, (BB*LQ)/128, 3), 512>>>(
        query, key, value, Wq, bq, Wk, bk, Wv, bv);

    score_kernel<<<dim3(LK/32, LQ/32, BB), 256>>>(Ws, bs);

    softmax_kernel<<<BB*LQ, 256>>>(wts);

    av_kernel<<<dim3(LQ/8, BB), 384>>>(wts, att);
}